// round 5
// baseline (speedup 1.0000x reference)
#include <cuda_runtime.h>

// mailbox: [N=50000, DEG=32, FEAT=128] float32 (row-major, f contiguous)
// out:     [N, FEAT] float32, out[n][f] = mean over deg of mailbox[n][d][f]
//
// Vectorized as float4: FEAT4 = 32 float4 per row. One thread per (n, f4).
// A warp (32 threads x float4) covers exactly one 512B neighbor row -> every
// load is a fully-coalesced 128B-line access; the warp streams the node's
// 16KB contiguously. Fully unrolled deg loop front-batches 32 LDG.128 for
// high MLP to hide DRAM latency. Pure HBM-bound: ~845MB traffic.

#define N_NODES 50000
#define MAX_DEG 32
#define FEAT4   32              // 128 floats / 4
#define TOTAL4  (N_NODES * FEAT4)   // 1,600,000 float4 outputs

__global__ void __launch_bounds__(256, 8)
mean_agg_kernel(const float4* __restrict__ mailbox, float4* __restrict__ out) {
    int idx = blockIdx.x * blockDim.x + threadIdx.x;   // (n * FEAT4 + f4)
    if (idx >= TOTAL4) return;

    int n  = idx >> 5;          // / FEAT4
    int f4 = idx & 31;          // % FEAT4

    // base of this node's mailbox in float4 units: n * DEG * FEAT4
    const float4* p = mailbox + ((long long)n * (MAX_DEG * FEAT4)) + f4;

    float4 acc = make_float4(0.f, 0.f, 0.f, 0.f);
#pragma unroll
    for (int d = 0; d < MAX_DEG; ++d) {
        float4 v = p[d * FEAT4];
        acc.x += v.x;
        acc.y += v.y;
        acc.z += v.z;
        acc.w += v.w;
    }

    const float inv = 1.0f / (float)MAX_DEG;
    acc.x *= inv; acc.y *= inv; acc.z *= inv; acc.w *= inv;
    out[idx] = acc;
}

extern "C" void kernel_launch(void* const* d_in, const int* in_sizes, int n_in,
                              void* d_out, int out_size) {
    const float4* mailbox = (const float4*)d_in[0];
    float4* out = (float4*)d_out;
    const int threads = 256;
    const int blocks = (TOTAL4 + threads - 1) / threads;  // 6250
    mean_agg_kernel<<<blocks, threads>>>(mailbox, out);
}